// round 1
// baseline (speedup 1.0000x reference)
#include <cuda_runtime.h>

#define BB   16
#define NN   128
#define HH   32
#define DD   5
#define NEFF 3
#define NE1  1537     // NUM_EDGES + 1
#define NP1  129      // N + 1

// Fused table: T[d][e][k] = sum_h edge_encoder_w[e,h] * Wdis[d,h,k]
// 5 * 1537 * 32 * 4 B = 983,680 B  (static device scratch; allowed)
__device__ float g_T[DD * NE1 * HH];

// ---------------------------------------------------------------------------
// Prologue: build the fused gather table. grid=(ceil(1537/8), 5), block=(32,8)
// ---------------------------------------------------------------------------
__global__ void build_table_kernel(const float* __restrict__ E,     // (1537, 32)
                                   const float* __restrict__ Wdis)  // (>=5*32*32,)
{
    const int d  = blockIdx.y;
    const int k  = threadIdx.x;       // output channel
    const int ey = threadIdx.y;       // edge-row within block
    const int e  = blockIdx.x * 8 + ey;

    __shared__ float Ws[HH * HH];     // Wdis[d][h][k]
    __shared__ float Es[8][HH];

    const int t = ey * 32 + k;
    for (int i = t; i < HH * HH; i += 256)
        Ws[i] = Wdis[d * HH * HH + i];
    Es[ey][k] = (e < NE1) ? E[e * HH + k] : 0.f;
    __syncthreads();

    if (e < NE1) {
        float acc = 0.f;
#pragma unroll
        for (int h = 0; h < HH; ++h)
            acc += Es[ey][h] * Ws[h * HH + k];
        g_T[(d * NE1 + e) * HH + k] = acc;
    }
}

// ---------------------------------------------------------------------------
// Main: one block per (output row i, batch b). grid=(129, 16), block=256.
//   i==0  -> virtual-token row:   out = 2*ab + virt[h]
//   i>=1  -> pair row ip=i-1:     out[j==0] = 2*ab + virt[h]
//                                 out[j>=1] = 2*ab + struct + edge-term
// ---------------------------------------------------------------------------
__global__ __launch_bounds__(256)
void bias_kernel(const float* __restrict__ ab,        // (B, 129, 129)
                 const int*   __restrict__ spat,      // (B, 128, 128)
                 const int*   __restrict__ edge,      // (B, 128, 128, 5, 3)
                 const float* __restrict__ struct_w,  // (512, 32)
                 const float* __restrict__ virt,      // (1, 32)
                 float*       __restrict__ out)       // (B, 32, 129, 129)
{
    const int b   = blockIdx.y;
    const int io  = blockIdx.x;       // output row 0..128
    const int tid = threadIdx.x;

    __shared__ float ab_s[NP1];
    __shared__ float vs[HH];
    __shared__ float row[NN * 33];    // [j][h], padded stride 33

    if (tid < HH)  vs[tid]  = virt[tid];
    if (tid < NP1) ab_s[tid] = ab[(b * NP1 + io) * NP1 + tid];

    if (io == 0) {
        __syncthreads();
        for (int idx = tid; idx < HH * NP1; idx += 256) {
            const int h = idx / NP1, j = idx % NP1;
            out[((b * HH + h) * NP1 + 0) * NP1 + j] = 2.f * ab_s[j] + vs[h];
        }
        return;
    }

    const int ip   = io - 1;
    const int warp = tid >> 5;
    const int lane = tid & 31;

    // Phase 1: per-pair edge term + structural bias, warp per pair.
    for (int j = warp; j < NN; j += 8) {
        const int pair = (b * NN + ip) * NN + j;
        const int* ep  = edge + pair * (DD * NEFF);

        int myidx = (lane < DD * NEFF) ? ep[lane] : 0;

        float acc = 0.f;
#pragma unroll
        for (int t = 0; t < DD * NEFF; ++t) {
            const int e = __shfl_sync(0xffffffffu, myidx, t);
            const int d = t / NEFF;
            acc += g_T[(d * NE1 + e) * HH + lane];
        }

        const int spv = spat[pair];
        const int sp  = (spv <= 1) ? 1 : min(spv - 1, DD);
        acc *= 1.f / (3.f * (float)sp);

        acc += struct_w[spv * HH + lane];
        row[j * 33 + lane] = acc;
    }
    __syncthreads();

    // Phase 2: emit 32 x 129 output slab, coalesced over j.
    for (int idx = tid; idx < HH * NP1; idx += 256) {
        const int h = idx / NP1, j = idx % NP1;
        const float add = (j == 0) ? vs[h] : row[(j - 1) * 33 + h];
        out[((b * HH + h) * NP1 + io) * NP1 + j] = 2.f * ab_s[j] + add;
    }
}

// ---------------------------------------------------------------------------
extern "C" void kernel_launch(void* const* d_in, const int* in_sizes, int n_in,
                              void* d_out, int out_size)
{
    // metadata order: x, attn_bias, spatial_pos, edge_input,
    //                 edge_encoder_w, structural_w, edge_dis_w, virt_w
    const float* ab    = (const float*)d_in[1];
    const int*   spat  = (const int*)  d_in[2];
    const int*   edge  = (const int*)  d_in[3];
    const float* ew    = (const float*)d_in[4];
    const float* sw    = (const float*)d_in[5];
    const float* wdis  = (const float*)d_in[6];
    const float* virt  = (const float*)d_in[7];
    float*       outp  = (float*)d_out;

    build_table_kernel<<<dim3((NE1 + 7) / 8, DD), dim3(32, 8)>>>(ew, wdis);
    bias_kernel<<<dim3(NP1, BB), 256>>>(ab, spat, edge, sw, virt, outp);
}

// round 3
// speedup vs baseline: 1.1759x; 1.1759x over previous
#include <cuda_runtime.h>

#define BB   16
#define NN   128
#define HH   32
#define DD   5
#define NE1  1537     // NUM_EDGES + 1
#define NP1  129      // N + 1
#define RST  34       // shared row stride (floats): even -> 8B-aligned float2 slots

// Fused table: T[d][e][k] = sum_h edge_encoder_w[e,h] * Wdis[d,h,k]
// Row e=0 is exactly zero (edge_encoder_w[0] == 0) — used as padding row.
// __align__(16) so float2 (LDG.64) access is always 8B-aligned.
__device__ __align__(16) float g_T[DD * NE1 * HH];

// ---------------------------------------------------------------------------
// Prologue: build the fused gather table. grid=(ceil(1537/8), 5), block=(32,8)
// ---------------------------------------------------------------------------
__global__ void build_table_kernel(const float* __restrict__ E,     // (1537, 32)
                                   const float* __restrict__ Wdis)  // (>=5*32*32,)
{
    const int d  = blockIdx.y;
    const int k  = threadIdx.x;
    const int ey = threadIdx.y;
    const int e  = blockIdx.x * 8 + ey;

    __shared__ float Ws[HH * HH];
    __shared__ float Es[8][HH];

    const int t = ey * 32 + k;
    for (int i = t; i < HH * HH; i += 256)
        Ws[i] = Wdis[d * HH * HH + i];
    Es[ey][k] = (e < NE1) ? E[e * HH + k] : 0.f;
    __syncthreads();

    if (e < NE1) {
        float acc = 0.f;
#pragma unroll
        for (int h = 0; h < HH; ++h)
            acc += Es[ey][h] * Ws[h * HH + k];
        g_T[(d * NE1 + e) * HH + k] = acc;
    }
}

// ---------------------------------------------------------------------------
// Main: one block per (output row io, batch b). grid=(129, 16), block=256.
// ---------------------------------------------------------------------------
__global__ __launch_bounds__(256)
void bias_kernel(const float* __restrict__ ab,        // (B, 129, 129)
                 const int*   __restrict__ spat,      // (B, 128, 128)
                 const int*   __restrict__ edge,      // (B, 128, 128, 5, 3)
                 const float* __restrict__ struct_w,  // (512, 32)
                 const float* __restrict__ virt,      // (1, 32)
                 float*       __restrict__ out)       // (B, 32, 129, 129)
{
    const int b   = blockIdx.y;
    const int io  = blockIdx.x;
    const int tid = threadIdx.x;
    const int warp = tid >> 5;
    const int lane = tid & 31;

    // row FIRST and 16B-aligned: every row[j*RST + 2*c2] is 8B-aligned.
    __shared__ __align__(16) float row[NN * RST];
    __shared__ float ab_s[NP1];
    __shared__ float vs[HH];

    if (tid < HH)  vs[tid]   = virt[tid];
    if (tid < NP1) ab_s[tid] = ab[(b * NP1 + io) * NP1 + tid];

    if (io == 0) {
        __syncthreads();
#pragma unroll
        for (int hh = 0; hh < 4; ++hh) {
            const int h = warp + hh * 8;
            const float vh = vs[h];
            float* ob = out + (((size_t)b * HH + h) * NP1) * NP1;
#pragma unroll
            for (int k = 0; k < 5; ++k) {
                const int j = lane + 32 * k;
                if (j < NP1) ob[j] = fmaf(2.f, ab_s[j], vh);
            }
        }
        return;
    }

    const int ip    = io - 1;
    const int pbase = (b * NN + ip) * NN;

    const int c2 = lane & 15;     // channel-pair index: channels 2*c2, 2*c2+1
    const int hi = lane >> 4;     // which of the 2 table rows this lane handles
    const float* Tlane = g_T + 2 * c2;

    // d = t/3 for t = 2*it + hi, per unrolled iteration (compile-time consts)
    const int d0c[8] = {0, 0, 1, 2, 2, 3, 4, 4};
    const int d1c[8] = {0, 1, 1, 2, 3, 3, 4, 4};

    for (int j = warp; j < NN; j += 8) {
        const int pair = pbase + j;
        const int* ep  = edge + (size_t)pair * 15;

        int myidx = (lane < 15) ? ep[lane] : 0;   // lane 15 -> 0 -> zero table row (pad)
        const int spv = spat[pair];

        unsigned long long acc;
        asm("mov.b64 %0, {%1, %2};" : "=l"(acc) : "f"(0.f), "f"(0.f));

#pragma unroll
        for (int it = 0; it < 8; ++it) {
            const int t = 2 * it + hi;
            const int e = __shfl_sync(0xffffffffu, myidx, t);
            const int d = hi ? d1c[it] : d0c[it];
            const unsigned long long v =
                *(const unsigned long long*)(Tlane + (d * NE1 + e) * HH);
            asm("add.rn.f32x2 %0, %0, %1;" : "+l"(acc) : "l"(v));
        }

        // combine the two 16-lane halves (each summed 8 of the 15 rows)
        unsigned int alo, ahw;
        asm("mov.b64 {%0, %1}, %2;" : "=r"(alo), "=r"(ahw) : "l"(acc));
        const unsigned int blo = __shfl_xor_sync(0xffffffffu, alo, 16);
        const unsigned int bhw = __shfl_xor_sync(0xffffffffu, ahw, 16);
        unsigned long long other;
        asm("mov.b64 %0, {%1, %2};" : "=l"(other) : "r"(blo), "r"(bhw));
        asm("add.rn.f32x2 %0, %0, %1;" : "+l"(acc) : "l"(other));

        if (hi == 0) {
            const int sp = (spv <= 1) ? 1 : min(spv - 1, DD);
            float s;
            asm("rcp.approx.f32 %0, %1;" : "=f"(s) : "f"(3.0f * (float)sp));
            unsigned long long ss;
            asm("mov.b64 %0, {%1, %1};" : "=l"(ss) : "f"(s));
            asm("mul.rn.f32x2 %0, %0, %1;" : "+l"(acc) : "l"(ss));

            const unsigned long long sv =
                *(const unsigned long long*)(struct_w + spv * HH + 2 * c2);
            asm("add.rn.f32x2 %0, %0, %1;" : "+l"(acc) : "l"(sv));

            *(unsigned long long*)&row[j * RST + 2 * c2] = acc;
        }
    }
    __syncthreads();

    // Phase 2: emit 32 x 129 slab; no div/mod, ab cached in registers.
    const int j1 = 1 + lane;
    const float a0 = ab_s[j1];
    const float a1 = ab_s[j1 + 32];
    const float a2 = ab_s[j1 + 64];
    const float a3 = ab_s[j1 + 96];
    const float az = ab_s[0];

#pragma unroll
    for (int hh = 0; hh < 4; ++hh) {
        const int h  = warp + hh * 8;
        const float vh = vs[h];
        float* ob = out + (((size_t)b * HH + h) * NP1 + io) * NP1;
        if (lane == 0) ob[0] = fmaf(2.f, az, vh);
        ob[j1]      = fmaf(2.f, a0, row[(lane)      * RST + h]);
        ob[j1 + 32] = fmaf(2.f, a1, row[(lane + 32) * RST + h]);
        ob[j1 + 64] = fmaf(2.f, a2, row[(lane + 64) * RST + h]);
        ob[j1 + 96] = fmaf(2.f, a3, row[(lane + 96) * RST + h]);
    }
}

// ---------------------------------------------------------------------------
extern "C" void kernel_launch(void* const* d_in, const int* in_sizes, int n_in,
                              void* d_out, int out_size)
{
    const float* ab    = (const float*)d_in[1];
    const int*   spat  = (const int*)  d_in[2];
    const int*   edge  = (const int*)  d_in[3];
    const float* ew    = (const float*)d_in[4];
    const float* sw    = (const float*)d_in[5];
    const float* wdis  = (const float*)d_in[6];
    const float* virt  = (const float*)d_in[7];
    float*       outp  = (float*)d_out;

    build_table_kernel<<<dim3((NE1 + 7) / 8, DD), dim3(32, 8)>>>(ew, wdis);
    bias_kernel<<<dim3(NP1, BB), 256>>>(ab, spat, edge, sw, virt, outp);
}

// round 4
// speedup vs baseline: 1.5621x; 1.3284x over previous
#include <cuda_runtime.h>

#define BB   16
#define NN   128
#define HH   32
#define DD   5
#define NE1  1537     // NUM_EDGES + 1
#define NP1  129      // N + 1
#define RST  33       // odd stride -> conflict-free smem row access

// Fused table: T[d][e][k] = sum_h edge_encoder_w[e,h] * Wdis[d,h,k]
// Row e=0 is exactly zero (edge_encoder_w[0] == 0).
__device__ __align__(16) float g_T[DD * NE1 * HH];

// ---------------------------------------------------------------------------
__global__ void build_table_kernel(const float* __restrict__ E,     // (1537, 32)
                                   const float* __restrict__ Wdis)  // (>=5*32*32,)
{
    const int d  = blockIdx.y;
    const int k  = threadIdx.x;
    const int ey = threadIdx.y;
    const int e  = blockIdx.x * 8 + ey;

    __shared__ float Ws[HH * HH];
    __shared__ float Es[8][HH];

    const int t = ey * 32 + k;
    for (int i = t; i < HH * HH; i += 256)
        Ws[i] = Wdis[d * HH * HH + i];
    Es[ey][k] = (e < NE1) ? E[e * HH + k] : 0.f;
    __syncthreads();

    if (e < NE1) {
        float acc = 0.f;
#pragma unroll
        for (int h = 0; h < HH; ++h)
            acc += Es[ey][h] * Ws[h * HH + k];
        g_T[(d * NE1 + e) * HH + k] = acc;
    }
}

// packed f32x2 helpers
#define F2_ZERO(a)      asm("mov.b64 %0, {%1, %1};" : "=l"(a) : "f"(0.f))
#define F2_ADD(a, v)    asm("add.rn.f32x2 %0, %0, %1;" : "+l"(a) : "l"(v))
#define F2_MULS(a, s)   do { unsigned long long _ss;                          \
                             asm("mov.b64 %0, {%1, %1};" : "=l"(_ss) : "f"(s));\
                             asm("mul.rn.f32x2 %0, %0, %1;" : "+l"(a) : "l"(_ss)); } while (0)

// ---------------------------------------------------------------------------
// Main: one block per (output row io, batch b). grid=(129, 16), block=256.
// ---------------------------------------------------------------------------
__global__ __launch_bounds__(256)
void bias_kernel(const float* __restrict__ ab,        // (B, 129, 129)
                 const int*   __restrict__ spat,      // (B, 128, 128)
                 const int*   __restrict__ edge,      // (B, 128, 128, 5, 3)
                 const float* __restrict__ struct_w,  // (512, 32)
                 const float* __restrict__ virt,      // (1, 32)
                 float*       __restrict__ out)       // (B, 32, 129, 129)
{
    const int b    = blockIdx.y;
    const int io   = blockIdx.x;
    const int tid  = threadIdx.x;
    const int warp = tid >> 5;
    const int lane = tid & 31;

    __shared__ __align__(16) int   sidx[NN * 16];   // indices, padded 15->16/pair
    __shared__ int   sspat[NN];
    __shared__ float row[NN * RST];                 // [pair][channel]
    __shared__ float ab_s[NP1];
    __shared__ float vs[HH];

    if (tid < HH)  vs[tid]   = virt[tid];
    if (tid < NP1) ab_s[tid] = ab[(b * NP1 + io) * NP1 + tid];

    if (io == 0) {
        __syncthreads();
#pragma unroll
        for (int hh = 0; hh < 4; ++hh) {
            const int h = warp + hh * 8;
            const float vh = vs[h];
            float* ob = out + (((size_t)b * HH + h) * NP1) * NP1;
#pragma unroll
            for (int k = 0; k < 5; ++k) {
                const int j = lane + 32 * k;
                if (j < NP1) ob[j] = fmaf(2.f, ab_s[j], vh);
            }
        }
        return;
    }

    const int ip    = io - 1;
    const int pbase = (b * NN + ip) * NN;

    // ---- stage indices (coalesced) into padded smem ----
    {
        const int* gsrc = edge + (size_t)pbase * 15;
#pragma unroll
        for (int it = 0; it < 8; ++it) {
            const int i = tid + it * 256;
            if (i < NN * 15)
                sidx[(i / 15) * 16 + (i % 15)] = gsrc[i];
        }
        if (tid < NN) sspat[tid] = spat[pbase + tid];
    }
    __syncthreads();

    // ---- phase 1: half-warp per pair, 2 pairs per warp-iteration ----
    const int c   = lane & 15;       // channel pair: channels 2c, 2c+1
    const int hi2 = lane >> 4;       // which pair of the two this half handles
    const float* Tc = g_T + 2 * c;
    const float* T0 = Tc;
    const float* T1 = Tc + 1 * NE1 * HH;
    const float* T2 = Tc + 2 * NE1 * HH;
    const float* T3 = Tc + 3 * NE1 * HH;
    const float* T4 = Tc + 4 * NE1 * HH;

#pragma unroll 2
    for (int k = 0; k < 8; ++k) {
        const int jh = 16 * k + 2 * warp + hi2;
        const int4 q0 = *(const int4*)&sidx[jh * 16 + 0];
        const int4 q1 = *(const int4*)&sidx[jh * 16 + 4];
        const int4 q2 = *(const int4*)&sidx[jh * 16 + 8];
        const int4 q3 = *(const int4*)&sidx[jh * 16 + 12];  // .w unused pad
        const int spv = sspat[jh];

        unsigned long long a0, a1;
        F2_ZERO(a0); F2_ZERO(a1);

        // d = t/3, t = 0..14
        F2_ADD(a0, *(const unsigned long long*)(T0 + q0.x * HH));
        F2_ADD(a1, *(const unsigned long long*)(T0 + q0.y * HH));
        F2_ADD(a0, *(const unsigned long long*)(T0 + q0.z * HH));
        F2_ADD(a1, *(const unsigned long long*)(T1 + q0.w * HH));
        F2_ADD(a0, *(const unsigned long long*)(T1 + q1.x * HH));
        F2_ADD(a1, *(const unsigned long long*)(T1 + q1.y * HH));
        F2_ADD(a0, *(const unsigned long long*)(T2 + q1.z * HH));
        F2_ADD(a1, *(const unsigned long long*)(T2 + q1.w * HH));
        F2_ADD(a0, *(const unsigned long long*)(T2 + q2.x * HH));
        F2_ADD(a1, *(const unsigned long long*)(T3 + q2.y * HH));
        F2_ADD(a0, *(const unsigned long long*)(T3 + q2.z * HH));
        F2_ADD(a1, *(const unsigned long long*)(T3 + q2.w * HH));
        F2_ADD(a0, *(const unsigned long long*)(T4 + q3.x * HH));
        F2_ADD(a1, *(const unsigned long long*)(T4 + q3.y * HH));
        F2_ADD(a0, *(const unsigned long long*)(T4 + q3.z * HH));
        F2_ADD(a0, a1);

        const int sp = (spv <= 1) ? 1 : min(spv - 1, DD);
        float s;
        asm("rcp.approx.f32 %0, %1;" : "=f"(s) : "f"(3.0f * (float)sp));
        F2_MULS(a0, s);

        F2_ADD(a0, *(const unsigned long long*)(struct_w + spv * HH + 2 * c));

        float rlo, rhi;
        asm("mov.b64 {%0, %1}, %2;" : "=f"(rlo), "=f"(rhi) : "l"(a0));
        row[jh * RST + 2 * c]     = rlo;
        row[jh * RST + 2 * c + 1] = rhi;
    }
    __syncthreads();

    // ---- phase 2: emit 32 x 129 slab; no div/mod, conflict-free LDS ----
    const int j1 = 1 + lane;
    const float a0 = ab_s[j1];
    const float a1 = ab_s[j1 + 32];
    const float a2 = ab_s[j1 + 64];
    const float a3 = ab_s[j1 + 96];
    const float az = ab_s[0];

#pragma unroll
    for (int hh = 0; hh < 4; ++hh) {
        const int h  = warp + hh * 8;
        const float vh = vs[h];
        float* ob = out + (((size_t)b * HH + h) * NP1 + io) * NP1;
        if (lane == 0) ob[0] = fmaf(2.f, az, vh);
        ob[j1]      = fmaf(2.f, a0, row[(lane)      * RST + h]);
        ob[j1 + 32] = fmaf(2.f, a1, row[(lane + 32) * RST + h]);
        ob[j1 + 64] = fmaf(2.f, a2, row[(lane + 64) * RST + h]);
        ob[j1 + 96] = fmaf(2.f, a3, row[(lane + 96) * RST + h]);
    }
}

// ---------------------------------------------------------------------------
extern "C" void kernel_launch(void* const* d_in, const int* in_sizes, int n_in,
                              void* d_out, int out_size)
{
    const float* ab    = (const float*)d_in[1];
    const int*   spat  = (const int*)  d_in[2];
    const int*   edge  = (const int*)  d_in[3];
    const float* ew    = (const float*)d_in[4];
    const float* sw    = (const float*)d_in[5];
    const float* wdis  = (const float*)d_in[6];
    const float* virt  = (const float*)d_in[7];
    float*       outp  = (float*)d_out;

    build_table_kernel<<<dim3((NE1 + 7) / 8, DD), dim3(32, 8)>>>(ew, wdis);
    bias_kernel<<<dim3(NP1, BB), 256>>>(ab, spat, edge, sw, virt, outp);
}

// round 5
// speedup vs baseline: 1.7173x; 1.0994x over previous
#include <cuda_runtime.h>

#define BB   16
#define NN   128
#define HH   32
#define DD   5
#define NE1  1537     // NUM_EDGES + 1
#define NP1  129      // N + 1
#define RST  33       // odd stride -> conflict-free smem row access

// Fused table: T[d][e][k] = sum_h edge_encoder_w[e,h] * Wdis[d,h,k]
// Row e=0 is exactly zero (edge_encoder_w[0] == 0).
__device__ __align__(16) float g_T[DD * NE1 * HH];

// ---------------------------------------------------------------------------
__global__ void build_table_kernel(const float* __restrict__ E,     // (1537, 32)
                                   const float* __restrict__ Wdis)  // (>=5*32*32,)
{
    const int d  = blockIdx.y;
    const int k  = threadIdx.x;
    const int ey = threadIdx.y;
    const int e  = blockIdx.x * 8 + ey;

    __shared__ float Ws[HH * HH];
    __shared__ float Es[8][HH];

    const int t = ey * 32 + k;
    for (int i = t; i < HH * HH; i += 256)
        Ws[i] = Wdis[d * HH * HH + i];
    Es[ey][k] = (e < NE1) ? E[e * HH + k] : 0.f;
    __syncthreads();

    if (e < NE1) {
        float acc = 0.f;
#pragma unroll
        for (int h = 0; h < HH; ++h)
            acc += Es[ey][h] * Ws[h * HH + k];
        g_T[(d * NE1 + e) * HH + k] = acc;
    }
}

// packed f32x2 helpers
#define F2_ZERO(a)      asm("mov.b64 %0, {%1, %1};" : "=l"(a) : "f"(0.f))
#define F2_ADD(a, v)    asm("add.rn.f32x2 %0, %0, %1;" : "+l"(a) : "l"(v))
#define F2_MULS(a, s)   do { unsigned long long _ss;                          \
                             asm("mov.b64 %0, {%1, %1};" : "=l"(_ss) : "f"(s));\
                             asm("mul.rn.f32x2 %0, %0, %1;" : "+l"(a) : "l"(_ss)); } while (0)

// ---------------------------------------------------------------------------
// Main: one block per (output row io, batch b). grid=(129, 16), block=256.
// ---------------------------------------------------------------------------
__global__ __launch_bounds__(256, 4)
void bias_kernel(const float* __restrict__ ab,        // (B, 129, 129)
                 const int*   __restrict__ spat,      // (B, 128, 128)
                 const int*   __restrict__ edge,      // (B, 128, 128, 5, 3)
                 const float* __restrict__ struct_w,  // (512, 32)
                 const float* __restrict__ virt,      // (1, 32)
                 float*       __restrict__ out)       // (B, 32, 129, 129)
{
    const int b    = blockIdx.y;
    const int io   = blockIdx.x;
    const int tid  = threadIdx.x;
    const int warp = tid >> 5;
    const int lane = tid & 31;

    __shared__ __align__(16) int   sidx[NN * 16];   // indices, padded 15->16/pair
    __shared__ int   sspat[NN];
    __shared__ float row[NN * RST];                 // [pair][channel]
    __shared__ float ab_s[NP1];
    __shared__ float vs[HH];

    if (tid < HH)  vs[tid]   = virt[tid];
    if (tid < NP1) ab_s[tid] = ab[(b * NP1 + io) * NP1 + tid];

    if (io == 0) {
        __syncthreads();
#pragma unroll
        for (int hh = 0; hh < 4; ++hh) {
            const int h = warp + hh * 8;
            const float vh = vs[h];
            float* ob = out + (((size_t)b * HH + h) * NP1) * NP1;
#pragma unroll
            for (int k = 0; k < 5; ++k) {
                const int j = lane + 32 * k;
                if (j < NP1) ob[j] = fmaf(2.f, ab_s[j], vh);
            }
        }
        return;
    }

    const int ip    = io - 1;
    const int pbase = (b * NN + ip) * NN;

    // ---- stage indices (coalesced) into padded smem ----
    {
        const int* gsrc = edge + (size_t)pbase * 15;
#pragma unroll
        for (int it = 0; it < 8; ++it) {
            const int i = tid + it * 256;
            if (i < NN * 15)
                sidx[(i / 15) * 16 + (i % 15)] = gsrc[i];
        }
        if (tid < NN) sspat[tid] = spat[pbase + tid];
    }
    __syncthreads();

    // ---- phase 1: half-warp per pair, all 15 gathers in flight at once ----
    const int c   = lane & 15;       // channel pair: channels 2c, 2c+1
    const int hi2 = lane >> 4;       // which pair of the two this half handles
    const float* Tc = g_T + 2 * c;
    const float* T0 = Tc;
    const float* T1 = Tc + 1 * NE1 * HH;
    const float* T2 = Tc + 2 * NE1 * HH;
    const float* T3 = Tc + 3 * NE1 * HH;
    const float* T4 = Tc + 4 * NE1 * HH;

#pragma unroll 1
    for (int k = 0; k < 8; ++k) {
        const int jh = 16 * k + 2 * warp + hi2;
        const int4 q0 = *(const int4*)&sidx[jh * 16 + 0];
        const int4 q1 = *(const int4*)&sidx[jh * 16 + 4];
        const int4 q2 = *(const int4*)&sidx[jh * 16 + 8];
        const int4 q3 = *(const int4*)&sidx[jh * 16 + 12];  // .w unused pad
        const int spv = sspat[jh];

        // Issue all 15 gathers back-to-back (d = t/3, t = 0..14).
        unsigned long long v0  = *(const unsigned long long*)(T0 + q0.x * HH);
        unsigned long long v1  = *(const unsigned long long*)(T0 + q0.y * HH);
        unsigned long long v2  = *(const unsigned long long*)(T0 + q0.z * HH);
        unsigned long long v3  = *(const unsigned long long*)(T1 + q0.w * HH);
        unsigned long long v4  = *(const unsigned long long*)(T1 + q1.x * HH);
        unsigned long long v5  = *(const unsigned long long*)(T1 + q1.y * HH);
        unsigned long long v6  = *(const unsigned long long*)(T2 + q1.z * HH);
        unsigned long long v7  = *(const unsigned long long*)(T2 + q1.w * HH);
        unsigned long long v8  = *(const unsigned long long*)(T2 + q2.x * HH);
        unsigned long long v9  = *(const unsigned long long*)(T3 + q2.y * HH);
        unsigned long long v10 = *(const unsigned long long*)(T3 + q2.z * HH);
        unsigned long long v11 = *(const unsigned long long*)(T3 + q2.w * HH);
        unsigned long long v12 = *(const unsigned long long*)(T4 + q3.x * HH);
        unsigned long long v13 = *(const unsigned long long*)(T4 + q3.y * HH);
        unsigned long long v14 = *(const unsigned long long*)(T4 + q3.z * HH);
        unsigned long long sv  =
            *(const unsigned long long*)(struct_w + spv * HH + 2 * c);

        // depth-4 pairwise reduction in packed f32x2
        F2_ADD(v0,  v1);   F2_ADD(v2,  v3);   F2_ADD(v4,  v5);
        F2_ADD(v6,  v7);   F2_ADD(v8,  v9);   F2_ADD(v10, v11);
        F2_ADD(v12, v13);
        F2_ADD(v0,  v2);   F2_ADD(v4,  v6);   F2_ADD(v8,  v10);
        F2_ADD(v12, v14);
        F2_ADD(v0,  v4);   F2_ADD(v8,  v12);
        F2_ADD(v0,  v8);

        const int sp = (spv <= 1) ? 1 : min(spv - 1, DD);
        float s;
        asm("rcp.approx.f32 %0, %1;" : "=f"(s) : "f"(3.0f * (float)sp));
        F2_MULS(v0, s);
        F2_ADD(v0, sv);

        float rlo, rhi;
        asm("mov.b64 {%0, %1}, %2;" : "=f"(rlo), "=f"(rhi) : "l"(v0));
        row[jh * RST + 2 * c]     = rlo;
        row[jh * RST + 2 * c + 1] = rhi;
    }
    __syncthreads();

    // ---- phase 2: emit 32 x 129 slab; no div/mod, conflict-free LDS ----
    const int j1 = 1 + lane;
    const float a0 = ab_s[j1];
    const float a1 = ab_s[j1 + 32];
    const float a2 = ab_s[j1 + 64];
    const float a3 = ab_s[j1 + 96];
    const float az = ab_s[0];

#pragma unroll
    for (int hh = 0; hh < 4; ++hh) {
        const int h  = warp + hh * 8;
        const float vh = vs[h];
        float* ob = out + (((size_t)b * HH + h) * NP1 + io) * NP1;
        if (lane == 0) ob[0] = fmaf(2.f, az, vh);
        ob[j1]      = fmaf(2.f, a0, row[(lane)      * RST + h]);
        ob[j1 + 32] = fmaf(2.f, a1, row[(lane + 32) * RST + h]);
        ob[j1 + 64] = fmaf(2.f, a2, row[(lane + 64) * RST + h]);
        ob[j1 + 96] = fmaf(2.f, a3, row[(lane + 96) * RST + h]);
    }
}

// ---------------------------------------------------------------------------
extern "C" void kernel_launch(void* const* d_in, const int* in_sizes, int n_in,
                              void* d_out, int out_size)
{
    const float* ab    = (const float*)d_in[1];
    const int*   spat  = (const int*)  d_in[2];
    const int*   edge  = (const int*)  d_in[3];
    const float* ew    = (const float*)d_in[4];
    const float* sw    = (const float*)d_in[5];
    const float* wdis  = (const float*)d_in[6];
    const float* virt  = (const float*)d_in[7];
    float*       outp  = (float*)d_out;

    build_table_kernel<<<dim3((NE1 + 7) / 8, DD), dim3(32, 8)>>>(ew, wdis);
    bias_kernel<<<dim3(NP1, BB), 256>>>(ab, spat, edge, sw, virt, outp);
}

// round 6
// speedup vs baseline: 1.9119x; 1.1133x over previous
#include <cuda_runtime.h>
#include <cuda_bf16.h>

#define BB   16
#define NN   128
#define HH   32
#define DD   5
#define NE1  1537     // NUM_EDGES + 1
#define NP1  129      // N + 1
#define RST  33       // odd stride -> conflict-free smem row access

// Fused table in bf16: Tb[d][e][k] = bf16( sum_h E[e,h] * Wdis[d,h,k] )
// Row e=0 is exactly zero (edge_encoder_w[0] == 0).
__device__ __align__(16) __nv_bfloat16 g_Tb[DD * NE1 * HH];

// ---------------------------------------------------------------------------
__global__ void build_table_kernel(const float* __restrict__ E,     // (1537, 32)
                                   const float* __restrict__ Wdis)  // (>=5*32*32,)
{
    const int d  = blockIdx.y;
    const int k  = threadIdx.x;
    const int ey = threadIdx.y;
    const int e  = blockIdx.x * 8 + ey;

    __shared__ float Ws[HH * HH];
    __shared__ float Es[8][HH];

    const int t = ey * 32 + k;
    for (int i = t; i < HH * HH; i += 256)
        Ws[i] = Wdis[d * HH * HH + i];
    Es[ey][k] = (e < NE1) ? E[e * HH + k] : 0.f;
    __syncthreads();

    if (e < NE1) {
        float acc = 0.f;
#pragma unroll
        for (int h = 0; h < HH; ++h)
            acc += Es[ey][h] * Ws[h * HH + k];
        g_Tb[(d * NE1 + e) * HH + k] = __float2bfloat16_rn(acc);
    }
}

// packed bf16x2 add (HADD2.BF16_V2, alu pipe)
#define BF2_ADD(a, b) asm("add.rn.bf16x2 %0, %0, %1;" : "+r"(a) : "r"(b))

// ---------------------------------------------------------------------------
// Main: one block per (output row io, batch b). grid=(129, 16), block=256.
// ---------------------------------------------------------------------------
__global__ __launch_bounds__(256, 4)
void bias_kernel(const float* __restrict__ ab,        // (B, 129, 129)
                 const int*   __restrict__ spat,      // (B, 128, 128)
                 const int*   __restrict__ edge,      // (B, 128, 128, 5, 3)
                 const float* __restrict__ struct_w,  // (512, 32)
                 const float* __restrict__ virt,      // (1, 32)
                 float*       __restrict__ out)       // (B, 32, 129, 129)
{
    const int b    = blockIdx.y;
    const int io   = blockIdx.x;
    const int tid  = threadIdx.x;
    const int warp = tid >> 5;
    const int lane = tid & 31;

    __shared__ __align__(16) int   sidx[NN * 16];   // indices, padded 15->16/pair
    __shared__ int   sspat[NN];
    __shared__ float row[NN * RST];                 // [pair][channel]
    __shared__ float ab_s[NP1];
    __shared__ float vs[HH];

    if (tid < HH)  vs[tid]   = virt[tid];
    if (tid < NP1) ab_s[tid] = ab[(b * NP1 + io) * NP1 + tid];

    if (io == 0) {
        __syncthreads();
#pragma unroll
        for (int hh = 0; hh < 4; ++hh) {
            const int h = warp + hh * 8;
            const float vh = vs[h];
            float* ob = out + (((size_t)b * HH + h) * NP1) * NP1;
#pragma unroll
            for (int k = 0; k < 5; ++k) {
                const int j = lane + 32 * k;
                if (j < NP1) ob[j] = fmaf(2.f, ab_s[j], vh);
            }
        }
        return;
    }

    const int ip    = io - 1;
    const int pbase = (b * NN + ip) * NN;

    // ---- stage indices (coalesced) into padded smem ----
    {
        const int* gsrc = edge + (size_t)pbase * 15;
#pragma unroll
        for (int it = 0; it < 8; ++it) {
            const int i = tid + it * 256;
            if (i < NN * 15)
                sidx[(i / 15) * 16 + (i % 15)] = gsrc[i];
        }
        if (tid < NN) sspat[tid] = spat[pbase + tid];
    }
    __syncthreads();

    // ---- phase 1: half-warp per pair, 15 bf16x2 gathers in flight ----
    const int c   = lane & 15;       // channel pair: channels 2c, 2c+1
    const int hi2 = lane >> 4;       // which of the 2 pairs this half handles
    const __nv_bfloat16* Tc = g_Tb + 2 * c;
    const __nv_bfloat16* T0 = Tc;
    const __nv_bfloat16* T1 = Tc + 1 * NE1 * HH;
    const __nv_bfloat16* T2 = Tc + 2 * NE1 * HH;
    const __nv_bfloat16* T3 = Tc + 3 * NE1 * HH;
    const __nv_bfloat16* T4 = Tc + 4 * NE1 * HH;

#pragma unroll 1
    for (int k = 0; k < 8; ++k) {
        const int jh = 16 * k + 2 * warp + hi2;
        const int4 q0 = *(const int4*)&sidx[jh * 16 + 0];
        const int4 q1 = *(const int4*)&sidx[jh * 16 + 4];
        const int4 q2 = *(const int4*)&sidx[jh * 16 + 8];
        const int4 q3 = *(const int4*)&sidx[jh * 16 + 12];  // .w unused pad
        const int spv = sspat[jh];

        // 15 independent bf16x2 gathers (d = t/3, t = 0..14)
        unsigned v0  = *(const unsigned*)(T0 + q0.x * HH);
        unsigned v1  = *(const unsigned*)(T0 + q0.y * HH);
        unsigned v2  = *(const unsigned*)(T0 + q0.z * HH);
        unsigned v3  = *(const unsigned*)(T1 + q0.w * HH);
        unsigned v4  = *(const unsigned*)(T1 + q1.x * HH);
        unsigned v5  = *(const unsigned*)(T1 + q1.y * HH);
        unsigned v6  = *(const unsigned*)(T2 + q1.z * HH);
        unsigned v7  = *(const unsigned*)(T2 + q1.w * HH);
        unsigned v8  = *(const unsigned*)(T2 + q2.x * HH);
        unsigned v9  = *(const unsigned*)(T3 + q2.y * HH);
        unsigned v10 = *(const unsigned*)(T3 + q2.z * HH);
        unsigned v11 = *(const unsigned*)(T3 + q2.w * HH);
        unsigned v12 = *(const unsigned*)(T4 + q3.x * HH);
        unsigned v13 = *(const unsigned*)(T4 + q3.y * HH);
        unsigned v14 = *(const unsigned*)(T4 + q3.z * HH);
        const unsigned long long sv =
            *(const unsigned long long*)(struct_w + spv * HH + 2 * c);

        // depth-4 pairwise bf16x2 reduction
        BF2_ADD(v0,  v1);   BF2_ADD(v2,  v3);   BF2_ADD(v4,  v5);
        BF2_ADD(v6,  v7);   BF2_ADD(v8,  v9);   BF2_ADD(v10, v11);
        BF2_ADD(v12, v13);
        BF2_ADD(v0,  v2);   BF2_ADD(v4,  v6);   BF2_ADD(v8,  v10);
        BF2_ADD(v12, v14);
        BF2_ADD(v0,  v4);   BF2_ADD(v8,  v12);
        BF2_ADD(v0,  v8);

        // widen bf16x2 -> 2x f32 (bf16 == high half of f32)
        const float flo = __uint_as_float(v0 << 16);
        const float fhi = __uint_as_float(v0 & 0xffff0000u);

        const int sp = (spv <= 1) ? 1 : min(spv - 1, DD);
        float s;
        asm("rcp.approx.f32 %0, %1;" : "=f"(s) : "f"(3.0f * (float)sp));

        float svlo, svhi;
        asm("mov.b64 {%0, %1}, %2;" : "=f"(svlo), "=f"(svhi) : "l"(sv));

        row[jh * RST + 2 * c]     = fmaf(flo, s, svlo);
        row[jh * RST + 2 * c + 1] = fmaf(fhi, s, svhi);
    }
    __syncthreads();

    // ---- phase 2: emit 32 x 129 slab; no div/mod, conflict-free LDS ----
    const int j1 = 1 + lane;
    const float a0 = ab_s[j1];
    const float a1 = ab_s[j1 + 32];
    const float a2 = ab_s[j1 + 64];
    const float a3 = ab_s[j1 + 96];
    const float az = ab_s[0];

#pragma unroll
    for (int hh = 0; hh < 4; ++hh) {
        const int h  = warp + hh * 8;
        const float vh = vs[h];
        float* ob = out + (((size_t)b * HH + h) * NP1 + io) * NP1;
        if (lane == 0) ob[0] = fmaf(2.f, az, vh);
        ob[j1]      = fmaf(2.f, a0, row[(lane)      * RST + h]);
        ob[j1 + 32] = fmaf(2.f, a1, row[(lane + 32) * RST + h]);
        ob[j1 + 64] = fmaf(2.f, a2, row[(lane + 64) * RST + h]);
        ob[j1 + 96] = fmaf(2.f, a3, row[(lane + 96) * RST + h]);
    }
}

// ---------------------------------------------------------------------------
extern "C" void kernel_launch(void* const* d_in, const int* in_sizes, int n_in,
                              void* d_out, int out_size)
{
    const float* ab    = (const float*)d_in[1];
    const int*   spat  = (const int*)  d_in[2];
    const int*   edge  = (const int*)  d_in[3];
    const float* ew    = (const float*)d_in[4];
    const float* sw    = (const float*)d_in[5];
    const float* wdis  = (const float*)d_in[6];
    const float* virt  = (const float*)d_in[7];
    float*       outp  = (float*)d_out;

    build_table_kernel<<<dim3((NE1 + 7) / 8, DD), dim3(32, 8)>>>(ew, wdis);
    bias_kernel<<<dim3(NP1, BB), 256>>>(ab, spat, edge, sw, virt, outp);
}

// round 7
// speedup vs baseline: 2.0721x; 1.0838x over previous
#include <cuda_runtime.h>
#include <cuda_bf16.h>

#define BB   16
#define NN   128
#define HH   32
#define DD   5
#define NE1  1537     // NUM_EDGES + 1
#define NP1  129      // N + 1
#define RST  33       // odd stride -> conflict-free smem row access (phase 2)
#define SST  20       // sidx stride (ints): 4 consecutive pairs hit distinct banks

// Fused table in bf16: Tb[d][e][k] = bf16( sum_h E[e,h] * Wdis[d,h,k] )
// Row e=0 is exactly zero (edge_encoder_w[0] == 0).
__device__ __align__(16) __nv_bfloat16 g_Tb[DD * NE1 * HH];

// ---------------------------------------------------------------------------
__global__ void build_table_kernel(const float* __restrict__ E,     // (1537, 32)
                                   const float* __restrict__ Wdis)  // (>=5*32*32,)
{
    const int d  = blockIdx.y;
    const int k  = threadIdx.x;
    const int ey = threadIdx.y;
    const int e  = blockIdx.x * 8 + ey;

    __shared__ float Ws[HH * HH];
    __shared__ float Es[8][HH];

    const int t = ey * 32 + k;
    for (int i = t; i < HH * HH; i += 256)
        Ws[i] = Wdis[d * HH * HH + i];
    Es[ey][k] = (e < NE1) ? E[e * HH + k] : 0.f;
    __syncthreads();

    if (e < NE1) {
        float acc = 0.f;
#pragma unroll
        for (int h = 0; h < HH; ++h)
            acc += Es[ey][h] * Ws[h * HH + k];
        g_Tb[(d * NE1 + e) * HH + k] = __float2bfloat16_rn(acc);
    }
}

// packed bf16x2 add (HADD2.BF16_V2, alu pipe)
#define BF2_ADD(a, b) asm("add.rn.bf16x2 %0, %0, %1;" : "+r"(a) : "r"(b))
#define ACC2(v)       do { BF2_ADD(a0, (v).x); BF2_ADD(a1, (v).y); } while (0)

// ---------------------------------------------------------------------------
// Main: one block per (output row io, batch b). grid=(129, 16), block=256.
// ---------------------------------------------------------------------------
__global__ __launch_bounds__(256, 3)
void bias_kernel(const float* __restrict__ ab,        // (B, 129, 129)
                 const int*   __restrict__ spat,      // (B, 128, 128)
                 const int*   __restrict__ edge,      // (B, 128, 128, 5, 3)
                 const float* __restrict__ struct_w,  // (512, 32)
                 const float* __restrict__ virt,      // (1, 32)
                 float*       __restrict__ out)       // (B, 32, 129, 129)
{
    const int b    = blockIdx.y;
    const int io   = blockIdx.x;
    const int tid  = threadIdx.x;
    const int warp = tid >> 5;
    const int lane = tid & 31;

    __shared__ __align__(16) int   sidx[NN * SST];  // indices, 15 used of SST/pair
    __shared__ int   sspat[NN];
    __shared__ float row[NN * RST];                 // [pair][channel]
    __shared__ float ab_s[NP1];
    __shared__ float vs[HH];

    if (tid < HH)  vs[tid]   = virt[tid];
    if (tid < NP1) ab_s[tid] = ab[(b * NP1 + io) * NP1 + tid];

    if (io == 0) {
        __syncthreads();
#pragma unroll
        for (int hh = 0; hh < 4; ++hh) {
            const int h = warp + hh * 8;
            const float vh = vs[h];
            float* ob = out + (((size_t)b * HH + h) * NP1) * NP1;
#pragma unroll
            for (int k = 0; k < 5; ++k) {
                const int j = lane + 32 * k;
                if (j < NP1) ob[j] = fmaf(2.f, ab_s[j], vh);
            }
        }
        return;
    }

    const int ip    = io - 1;
    const int pbase = (b * NN + ip) * NN;

    // ---- stage indices (coalesced) into padded smem ----
    {
        const int* gsrc = edge + (size_t)pbase * 15;
#pragma unroll
        for (int it = 0; it < 8; ++it) {
            const int i = tid + it * 256;
            if (i < NN * 15)
                sidx[(i / 15) * SST + (i % 15)] = gsrc[i];
        }
        if (tid < NN) sspat[tid] = spat[pbase + tid];
    }
    __syncthreads();

    // ---- phase 1: 8 lanes per pair, 4 pairs per warp-iteration ----
    const int g  = lane >> 3;          // pair group within warp (0..3)
    const int co = (lane & 7) * 4;     // this lane's 4 channels
    const __nv_bfloat16* Tco = g_Tb + co;
    const __nv_bfloat16* T0 = Tco;
    const __nv_bfloat16* T1 = Tco + 1 * NE1 * HH;
    const __nv_bfloat16* T2 = Tco + 2 * NE1 * HH;
    const __nv_bfloat16* T3 = Tco + 3 * NE1 * HH;
    const __nv_bfloat16* T4 = Tco + 4 * NE1 * HH;

#pragma unroll 1
    for (int k = 0; k < 4; ++k) {
        const int jh = k * 32 + warp * 4 + g;
        const int4 q0 = *(const int4*)&sidx[jh * SST + 0];
        const int4 q1 = *(const int4*)&sidx[jh * SST + 4];
        const int4 q2 = *(const int4*)&sidx[jh * SST + 8];
        const int4 q3 = *(const int4*)&sidx[jh * SST + 12];  // .w unused pad
        const int spv = sspat[jh];

        // 15 independent LDG.64 gathers (d = t/3, t = 0..14), 4 bf16 ch each
        const uint2 v0  = *(const uint2*)(T0 + q0.x * HH);
        const uint2 v1  = *(const uint2*)(T0 + q0.y * HH);
        const uint2 v2  = *(const uint2*)(T0 + q0.z * HH);
        const uint2 v3  = *(const uint2*)(T1 + q0.w * HH);
        const uint2 v4  = *(const uint2*)(T1 + q1.x * HH);
        const uint2 v5  = *(const uint2*)(T1 + q1.y * HH);
        const uint2 v6  = *(const uint2*)(T2 + q1.z * HH);
        const uint2 v7  = *(const uint2*)(T2 + q1.w * HH);
        const uint2 v8  = *(const uint2*)(T2 + q2.x * HH);
        const uint2 v9  = *(const uint2*)(T3 + q2.y * HH);
        const uint2 v10 = *(const uint2*)(T3 + q2.z * HH);
        const uint2 v11 = *(const uint2*)(T3 + q2.w * HH);
        const uint2 v12 = *(const uint2*)(T4 + q3.x * HH);
        const uint2 v13 = *(const uint2*)(T4 + q3.y * HH);
        const uint2 v14 = *(const uint2*)(T4 + q3.z * HH);
        const float4 sw = *(const float4*)(struct_w + spv * HH + co);

        unsigned a0 = 0, a1 = 0;
        ACC2(v0);  ACC2(v1);  ACC2(v2);  ACC2(v3);  ACC2(v4);
        ACC2(v5);  ACC2(v6);  ACC2(v7);  ACC2(v8);  ACC2(v9);
        ACC2(v10); ACC2(v11); ACC2(v12); ACC2(v13); ACC2(v14);

        // widen bf16x2 -> f32 (bf16 == high half of f32)
        const float f0 = __uint_as_float(a0 << 16);
        const float f1 = __uint_as_float(a0 & 0xffff0000u);
        const float f2 = __uint_as_float(a1 << 16);
        const float f3 = __uint_as_float(a1 & 0xffff0000u);

        const int sp = (spv <= 1) ? 1 : min(spv - 1, DD);
        float s;
        asm("rcp.approx.f32 %0, %1;" : "=f"(s) : "f"(3.0f * (float)sp));

        float* rp = &row[jh * RST + co];
        rp[0] = fmaf(f0, s, sw.x);
        rp[1] = fmaf(f1, s, sw.y);
        rp[2] = fmaf(f2, s, sw.z);
        rp[3] = fmaf(f3, s, sw.w);
    }
    __syncthreads();

    // ---- phase 2: emit 32 x 129 slab; no div/mod, conflict-free LDS ----
    const int j1 = 1 + lane;
    const float a0 = ab_s[j1];
    const float a1 = ab_s[j1 + 32];
    const float a2 = ab_s[j1 + 64];
    const float a3 = ab_s[j1 + 96];
    const float az = ab_s[0];

#pragma unroll
    for (int hh = 0; hh < 4; ++hh) {
        const int h  = warp + hh * 8;
        const float vh = vs[h];
        float* ob = out + (((size_t)b * HH + h) * NP1 + io) * NP1;
        if (lane == 0) ob[0] = fmaf(2.f, az, vh);
        ob[j1]      = fmaf(2.f, a0, row[(lane)      * RST + h]);
        ob[j1 + 32] = fmaf(2.f, a1, row[(lane + 32) * RST + h]);
        ob[j1 + 64] = fmaf(2.f, a2, row[(lane + 64) * RST + h]);
        ob[j1 + 96] = fmaf(2.f, a3, row[(lane + 96) * RST + h]);
    }
}

// ---------------------------------------------------------------------------
extern "C" void kernel_launch(void* const* d_in, const int* in_sizes, int n_in,
                              void* d_out, int out_size)
{
    const float* ab    = (const float*)d_in[1];
    const int*   spat  = (const int*)  d_in[2];
    const int*   edge  = (const int*)  d_in[3];
    const float* ew    = (const float*)d_in[4];
    const float* sw    = (const float*)d_in[5];
    const float* wdis  = (const float*)d_in[6];
    const float* virt  = (const float*)d_in[7];
    float*       outp  = (float*)d_out;

    build_table_kernel<<<dim3((NE1 + 7) / 8, DD), dim3(32, 8)>>>(ew, wdis);
    bias_kernel<<<dim3(NP1, BB), 256>>>(ab, spat, edge, sw, virt, outp);
}